// round 1
// baseline (speedup 1.0000x reference)
#include <cuda_runtime.h>
#include <cstdint>
#include <math.h>

// Problem constants
#define P     48
#define FLEN  168
#define HIST  336
#define HOFF  288   // HIST - P

// Precomputed affine map: out[b,t] = g_C[t] + sum_k g_G[k*FLEN+t] * enc_l[b*HIST+HOFF+k]
__device__ float g_G[P * FLEN];
__device__ float g_C[FLEN];
__device__ float g_lv;

typedef unsigned long long ull;

__device__ __forceinline__ ull pack2(float a, float b) {
    ull r; asm("mov.b64 %0, {%1, %2};" : "=l"(r) : "f"(a), "f"(b)); return r;
}
__device__ __forceinline__ void unpack2(ull v, float& a, float& b) {
    asm("mov.b64 {%0, %1}, %2;" : "=f"(a), "=f"(b) : "l"(v));
}
// Packed fp32x2 FMA (Blackwell 2x fp32 path; only emitted from PTX fma.rn.f32x2)
__device__ __forceinline__ ull ffma2(ull a, ull b, ull c) {
    ull d; asm("fma.rn.f32x2 %0, %1, %2, %3;" : "=l"(d) : "l"(a), "l"(b), "l"(c)); return d;
}

// ---------------------------------------------------------------------------
// Kernel 1: tiny precompute of the affine map (G, C, logvar const).
// The AR scan is affine in the initial window, so track the impulse response:
// h[k][i] = d(history[i]) / d(s0[k]) for k<P, and h[P] = constant term.
// Each of 49 threads owns one coefficient column; rows are independent.
// ---------------------------------------------------------------------------
__global__ void precompute_kernel(const float* __restrict__ phi,
                                  const float* __restrict__ bias,
                                  const float* __restrict__ log_sigma2,
                                  const float* __restrict__ mu_p,
                                  const float* __restrict__ sigma_p) {
    // 221 (odd) row pitch -> conflict-free across k when threads step together
    __shared__ float h[P + 1][221];
    const int k = threadIdx.x;

    float ph[P];
#pragma unroll
    for (int j = 0; j < P; j++) ph[j] = phi[j];

    if (k <= P) {
#pragma unroll
        for (int i = 0; i < P; i++) h[k][i] = (k == i) ? 1.0f : 0.0f;  // k==P row: all zeros
        const float b0 = (k == P) ? bias[0] : 0.0f;
        for (int t = 0; t < FLEN; t++) {
            float s0 = 0.f, s1 = 0.f, s2 = 0.f, s3 = 0.f;
#pragma unroll
            for (int j = 0; j < P; j += 4) {
                s0 += ph[j + 0] * h[k][t + j + 0];
                s1 += ph[j + 1] * h[k][t + j + 1];
                s2 += ph[j + 2] * h[k][t + j + 2];
                s3 += ph[j + 3] * h[k][t + j + 3];
            }
            h[k][P + t] = b0 + ((s0 + s1) + (s2 + s3));
        }
    }
    __syncthreads();

    const float mu = *mu_p;
    const float sg = *sigma_p;

    // Fold standardization + un-standardization into C:
    // out = mu + sg*c_t + sum_k W[t,k]*(y_raw - mu)
    //     = (mu + sg*c_t - mu*sum_k W[t,k]) + sum_k W[t,k]*y_raw
    for (int t = threadIdx.x; t < FLEN; t += blockDim.x) {
        float sum = 0.0f;
        for (int kk = 0; kk < P; kk++) sum += h[kk][P + t];
        g_C[t] = mu + sg * h[P][P + t] - mu * sum;
    }
    for (int idx = threadIdx.x; idx < P * FLEN; idx += blockDim.x) {
        const int kk = idx / FLEN;
        const int t  = idx - kk * FLEN;
        g_G[idx] = h[kk][P + t];
    }
    if (threadIdx.x == 0) g_lv = log_sigma2[0] + 2.0f * logf(sg);
}

// ---------------------------------------------------------------------------
// Kernel 2: the GEMM-like apply. Each thread handles TWO rows packed into the
// f32x2 lanes; 12 packed accumulators per t-pass; G broadcast from shared.
// ---------------------------------------------------------------------------
#define TPB 128
#define RPC 256  // rows per CTA = 2 * TPB

__global__ void __launch_bounds__(TPB)
forecast_kernel(const float* __restrict__ enc_l, float* __restrict__ out, int B) {
    __shared__ float Gs[P * FLEN];
    __shared__ float Cs[FLEN];

    for (int i = threadIdx.x; i < (P * FLEN) / 4; i += TPB)
        ((float4*)Gs)[i] = ((const float4*)g_G)[i];
    if (threadIdx.x < FLEN) Cs[threadIdx.x] = g_C[threadIdx.x];
    if (threadIdx.x + TPB < FLEN) Cs[threadIdx.x + TPB] = g_C[threadIdx.x + TPB];
    __syncthreads();

    const int b0 = blockIdx.x * RPC + threadIdx.x;
    if (b0 >= B) return;
    const int b1 = b0 + TPB;
    const bool has1 = (b1 < B);

    // Load the 48-float window tails of both rows, pack lanes (row0, row1).
    const float4* p0 = reinterpret_cast<const float4*>(enc_l + (size_t)b0 * HIST + HOFF);
    const float4* p1 = reinterpret_cast<const float4*>(enc_l + (size_t)(has1 ? b1 : b0) * HIST + HOFF);
    ull y2[P];
#pragma unroll
    for (int q = 0; q < 12; q++) {
        const float4 a = p0[q];
        const float4 c = p1[q];
        y2[4 * q + 0] = pack2(a.x, c.x);
        y2[4 * q + 1] = pack2(a.y, c.y);
        y2[4 * q + 2] = pack2(a.z, c.z);
        y2[4 * q + 3] = pack2(a.w, c.w);
    }

    float* o0 = out + (size_t)b0 * FLEN;
    float* o1 = out + (size_t)b1 * FLEN;

#pragma unroll 1
    for (int pass = 0; pass < 14; ++pass) {
        const int t0 = pass * 12;
        ull acc[12];
#pragma unroll
        for (int i = 0; i < 12; i++) {
            const float c = Cs[t0 + i];
            acc[i] = pack2(c, c);
        }
        const float2* gp = reinterpret_cast<const float2*>(Gs) + (t0 >> 1);
#pragma unroll 4
        for (int kk = 0; kk < P; ++kk) {
            const ull yv = y2[kk];
#pragma unroll
            for (int i = 0; i < 6; i++) {
                const float2 g = gp[i];
                acc[2 * i + 0] = ffma2(pack2(g.x, g.x), yv, acc[2 * i + 0]);
                acc[2 * i + 1] = ffma2(pack2(g.y, g.y), yv, acc[2 * i + 1]);
            }
            gp += FLEN / 2;
        }

        float r0[12], r1[12];
#pragma unroll
        for (int i = 0; i < 12; i++) unpack2(acc[i], r0[i], r1[i]);

        float4* w0 = reinterpret_cast<float4*>(o0 + t0);  // t0 multiple of 12 -> 48B aligned? 12*4=48, yes /16
        w0[0] = make_float4(r0[0], r0[1], r0[2], r0[3]);
        w0[1] = make_float4(r0[4], r0[5], r0[6], r0[7]);
        w0[2] = make_float4(r0[8], r0[9], r0[10], r0[11]);
        if (has1) {
            float4* w1 = reinterpret_cast<float4*>(o1 + t0);
            w1[0] = make_float4(r1[0], r1[1], r1[2], r1[3]);
            w1[1] = make_float4(r1[4], r1[5], r1[6], r1[7]);
            w1[2] = make_float4(r1[8], r1[9], r1[10], r1[11]);
        }
    }

    // logvar half: constant value broadcast
    const float lv = g_lv;
    const float4 lv4 = make_float4(lv, lv, lv, lv);
    float4* q0 = reinterpret_cast<float4*>(out + (size_t)B * FLEN + (size_t)b0 * FLEN);
#pragma unroll
    for (int i = 0; i < FLEN / 4; i++) q0[i] = lv4;
    if (has1) {
        float4* q1 = reinterpret_cast<float4*>(out + (size_t)B * FLEN + (size_t)b1 * FLEN);
#pragma unroll
        for (int i = 0; i < FLEN / 4; i++) q1[i] = lv4;
    }
}

// ---------------------------------------------------------------------------
extern "C" void kernel_launch(void* const* d_in, const int* in_sizes, int n_in,
                              void* d_out, int out_size) {
    const float* enc_l      = (const float*)d_in[0];
    // d_in[1..3] = enc_t, enc_w, enc_s (unused by the reference)
    const float* phi        = (const float*)d_in[4];
    const float* bias       = (const float*)d_in[5];
    const float* log_sigma2 = (const float*)d_in[6];
    const float* mu         = (const float*)d_in[7];
    const float* sigma      = (const float*)d_in[8];

    const int B = in_sizes[0] / HIST;

    precompute_kernel<<<1, 64>>>(phi, bias, log_sigma2, mu, sigma);

    const int nblk = (B + RPC - 1) / RPC;
    forecast_kernel<<<nblk, TPB>>>(enc_l, (float*)d_out, B);
}